// round 5
// baseline (speedup 1.0000x reference)
#include <cuda_runtime.h>
#include <math.h>

// out[b,k] = exp(-beta_k * max(||x_b||^2 + ||c_k||^2 - 2 x_b.c_k, 0))
// B=16384, K=4096, D=1024, fp32.
//
// fp32 exp(-t) == exactly 0.0f for t > ~104. Cauchy-Schwarz: d2 >= (||x_b||-||c_k||)^2.
// Precompute per-column interval [lo_k, hi_k] of ||x|| values for which the element
// is NOT provably zero; reduce to a global interval. Rows whose ||x_b|| falls outside
// the global interval are written as pure zeros (streaming stores, no math, no barrier).
// Rare rows inside the interval take a per-element interval test + exact fp32 dot+expf
// fallback, so the kernel is correct for arbitrary inputs.

#define B_ROWS 16384
#define K_COLS 4096
#define D_DIM  1024
#define THRESH 106.0f
#define RPB    8        // rows per block in the main kernel

__device__ float g_x2[B_ROWS];
__device__ float g_rx[B_ROWS];   // sqrt(||x_b||^2)
__device__ float g_c2[K_COLS];
__device__ float g_lo[K_COLS];
__device__ float g_hi[K_COLS];
__device__ float g_glo;          // min_k lo_k
__device__ float g_ghi;          // max_k hi_k

// ---------------------------------------------------------------------------
// Kernel 1: row norms. Rows [0,K): centers -> c2, lo, hi. Rows [K,K+B): x -> x2, rx.
// ---------------------------------------------------------------------------
__global__ void __launch_bounds__(256) norms_kernel(const float* __restrict__ x,
                                                    const float* __restrict__ c,
                                                    const float* __restrict__ betas) {
    const int row = blockIdx.x;
    const bool is_center = (row < K_COLS);
    const float* src = is_center ? (c + (size_t)row * D_DIM)
                                 : (x + (size_t)(row - K_COLS) * D_DIM);
    const int tid = threadIdx.x;
    float4 a = reinterpret_cast<const float4*>(src)[tid];
    float s = a.x * a.x + a.y * a.y + a.z * a.z + a.w * a.w;
    #pragma unroll
    for (int o = 16; o > 0; o >>= 1)
        s += __shfl_xor_sync(0xffffffffu, s, o);
    __shared__ float ws[8];
    if ((tid & 31) == 0) ws[tid >> 5] = s;
    __syncthreads();
    if (tid == 0) {
        float t = 0.f;
        #pragma unroll
        for (int i = 0; i < 8; i++) t += ws[i];
        if (is_center) {
            g_c2[row] = t;
            const float beta = betas[row];
            const float sk = sqrtf(t);
            float lo = -INFINITY, hi = INFINITY;
            if (beta > 0.0f && isfinite(sk)) {
                const float rk = sqrtf(THRESH / beta);
                if (isfinite(rk)) { lo = sk - rk; hi = sk + rk; }
            }
            // sanitize NaN -> infinite interval (always fallback)
            if (!(lo == lo)) lo = -INFINITY;
            if (!(hi == hi)) hi =  INFINITY;
            g_lo[row] = lo;
            g_hi[row] = hi;
        } else {
            g_x2[row - K_COLS] = t;
            g_rx[row - K_COLS] = sqrtf(t);
        }
    }
}

// ---------------------------------------------------------------------------
// Kernel 2: global reduce of [lo_k, hi_k] over all k.
// ---------------------------------------------------------------------------
__global__ void __launch_bounds__(256) glob_kernel() {
    __shared__ float slo[256], shi[256];
    float lo = INFINITY, hi = -INFINITY;
    for (int k = threadIdx.x; k < K_COLS; k += 256) {
        lo = fminf(lo, g_lo[k]);
        hi = fmaxf(hi, g_hi[k]);
    }
    slo[threadIdx.x] = lo;
    shi[threadIdx.x] = hi;
    __syncthreads();
    for (int s2 = 128; s2 > 0; s2 >>= 1) {
        if (threadIdx.x < s2) {
            slo[threadIdx.x] = fminf(slo[threadIdx.x], slo[threadIdx.x + s2]);
            shi[threadIdx.x] = fmaxf(shi[threadIdx.x], shi[threadIdx.x + s2]);
        }
        __syncthreads();
    }
    if (threadIdx.x == 0) { g_glo = slo[0]; g_ghi = shi[0]; }
}

// ---------------------------------------------------------------------------
// Kernel 3: main. Each block handles RPB consecutive rows. Per row a single
// block-uniform compare decides: pure zero-store stream, or slow exact path.
// ---------------------------------------------------------------------------
__global__ void __launch_bounds__(256) rbf_main(const float* __restrict__ x,
                                                const float* __restrict__ c,
                                                const float* __restrict__ betas,
                                                float* __restrict__ out) {
    const int tid = threadIdx.x;
    const int b0  = blockIdx.x * RPB;
    const float glo = g_glo;
    const float ghi = g_ghi;

    // prefetch RPB row norms (b0 is 8-aligned -> two aligned float4 loads)
    const float4 ra = reinterpret_cast<const float4*>(&g_rx[b0])[0];
    const float4 rb = reinterpret_cast<const float4*>(&g_rx[b0])[1];
    const float rx[RPB] = {ra.x, ra.y, ra.z, ra.w, rb.x, rb.y, rb.z, rb.w};

    __shared__ float xs[D_DIM];
    const float4 z = make_float4(0.f, 0.f, 0.f, 0.f);

    #pragma unroll
    for (int r = 0; r < RPB; r++) {
        const int b = b0 + r;
        const float t = rx[r];
        float4* __restrict__ orow =
            reinterpret_cast<float4*>(out + (size_t)b * K_COLS);
        if (t < glo || t > ghi) {
            // provably-zero row: streaming stores only
            #pragma unroll
            for (int j = 0; j < 4; j++) orow[tid + 256 * j] = z;
        } else {
            // slow path (block-uniform branch): stage x row, per-element test
            const float sx = g_x2[b];
            reinterpret_cast<float4*>(xs)[tid] =
                reinterpret_cast<const float4*>(x + (size_t)b * D_DIM)[tid];
            __syncthreads();
            #pragma unroll
            for (int j = 0; j < 4; j++) {
                const int kq = tid + 256 * j;          // float4 index
                const float4 lo4 = reinterpret_cast<const float4*>(g_lo)[kq];
                const float4 hi4 = reinterpret_cast<const float4*>(g_hi)[kq];
                const float lo_a[4] = {lo4.x, lo4.y, lo4.z, lo4.w};
                const float hi_a[4] = {hi4.x, hi4.y, hi4.z, hi4.w};
                float o[4];
                #pragma unroll
                for (int q = 0; q < 4; q++) {
                    if (t < lo_a[q] || t > hi_a[q]) {
                        o[q] = 0.0f;                   // provably zero
                    } else {
                        const int k = kq * 4 + q;
                        const float* __restrict__ cr = c + (size_t)k * D_DIM;
                        float dot = 0.f;
                        #pragma unroll 8
                        for (int i = 0; i < D_DIM; i++) dot = fmaf(xs[i], cr[i], dot);
                        const float d2 = fmaxf(sx + g_c2[k] - 2.0f * dot, 0.0f);
                        o[q] = expf(-betas[k] * d2);
                    }
                }
                orow[kq] = make_float4(o[0], o[1], o[2], o[3]);
            }
            __syncthreads();   // protect xs before next slow row
        }
    }
}

// ---------------------------------------------------------------------------
extern "C" void kernel_launch(void* const* d_in, const int* in_sizes, int n_in,
                              void* d_out, int out_size) {
    const float* x     = (const float*)d_in[0];
    const float* cent  = (const float*)d_in[1];
    const float* betas = (const float*)d_in[2];
    float* out = (float*)d_out;

    norms_kernel<<<K_COLS + B_ROWS, 256>>>(x, cent, betas);
    glob_kernel<<<1, 256>>>();
    rbf_main<<<B_ROWS / RPB, 256>>>(x, cent, betas, out);
}